// round 11
// baseline (speedup 1.0000x reference)
#include <cuda_runtime.h>
#include <cuda_fp16.h>
#include <cstdint>

#define T_STEPS 256
#define BSZ     25
#define VOCAB   32000
#define HID     1024
#define NCLS    2
#define MROWS   6400
#define NBLK_RECUR 128
#define KT      1000           // k-tiles of 32 (32000/32)
#define TILEB_A 8192           // packed A tile: 128 m x 32 k x fp16
#define TILEB_B 4096           // packed B tile:  64 n x 32 k x fp16
#define NS      3              // pipeline stages (3 x 12KB = 36KB dynamic smem)
#define STG_STRIDE 12288       // A tile + B tile per stage

// ---------------- device scratch ----------------
__device__ float g_Z[MROWS * HID];                          // 26 MB
__device__ float g_WhhT[HID * HID];                         // 4 MB
__device__ float g_h[2][BSZ * HID];
__device__ __align__(256) uint8_t g_Apk[(size_t)50 * KT * TILEB_A];  // 409.6 MB
__device__ __align__(256) uint8_t g_Bpk[(size_t)16 * KT * TILEB_B];  // 65.5 MB
__device__ int   g_flags[NBLK_RECUR * 32];
__device__ volatile int g_rel;

// ---------------- helpers ----------------
__device__ __forceinline__ uint32_t s2u(const void* p) {
    uint32_t a;
    asm("{ .reg .u64 t; cvta.to.shared.u64 t, %1; cvt.u32.u64 %0, t; }" : "=r"(a) : "l"(p));
    return a;
}
__device__ __forceinline__ void mbar_init(uint32_t m, uint32_t c) {
    asm volatile("mbarrier.init.shared.b64 [%0], %1;" :: "r"(m), "r"(c) : "memory");
}
__device__ __forceinline__ void mbar_expect(uint32_t m, uint32_t bytes) {
    asm volatile("mbarrier.arrive.expect_tx.shared.b64 _, [%0], %1;" :: "r"(m), "r"(bytes) : "memory");
}
__device__ __forceinline__ void mbar_arrive(uint32_t m) {
    asm volatile("mbarrier.arrive.shared.b64 _, [%0];" :: "r"(m) : "memory");
}
__device__ __forceinline__ void mbar_wait(uint32_t m, uint32_t ph) {
    asm volatile(
        "{\n\t.reg .pred P;\n\t"
        "W%=:\n\t"
        "mbarrier.try_wait.parity.acquire.cta.shared::cta.b64 P, [%0], %1, 0x989680;\n\t"
        "@P bra.uni D%=;\n\t"
        "bra.uni W%=;\n\t"
        "D%=:\n\t}" :: "r"(m), "r"(ph) : "memory");
}
__device__ __forceinline__ void bulk_g2s(uint32_t dst, const void* src, uint32_t bytes, uint32_t mbar) {
    asm volatile(
        "cp.async.bulk.shared::cluster.global.mbarrier::complete_tx::bytes [%0], [%1], %2, [%3];"
        :: "r"(dst), "l"(src), "r"(bytes), "r"(mbar) : "memory");
}
__device__ __forceinline__ void hmma(float* c, uint32_t a0, uint32_t a1, uint32_t a2,
                                     uint32_t a3, uint32_t b0, uint32_t b1) {
    asm volatile(
        "mma.sync.aligned.m16n8k16.row.col.f32.f16.f16.f32 "
        "{%0,%1,%2,%3}, {%4,%5,%6,%7}, {%8,%9}, {%0,%1,%2,%3};\n"
        : "+f"(c[0]), "+f"(c[1]), "+f"(c[2]), "+f"(c[3])
        : "r"(a0), "r"(a1), "r"(a2), "r"(a3), "r"(b0), "r"(b1));
}

// packed in-row byte offset for k-pair p within a 32-k row (fragment-ordered)
__device__ __forceinline__ uint32_t koff_pair(int p) {
    return (uint32_t)((p & 3) * 16 + (p >> 2) * 4);
}

// ---------------- init ----------------
__global__ void init_k() {
    int tid = blockIdx.x * 256 + threadIdx.x;
    if (tid == 0) g_rel = 0;
    if (tid < NBLK_RECUR * 32) g_flags[tid] = 0;
    if (tid < BSZ * HID) g_h[0][tid] = 0.0f;
}

// ---------------- W_hh transpose ----------------
__global__ void transpose_k(const float* __restrict__ W) {
    __shared__ float tile[32][33];
    int x = blockIdx.x * 32 + threadIdx.x;
    int y = blockIdx.y * 32 + threadIdx.y;
    #pragma unroll
    for (int i = 0; i < 32; i += 8)
        tile[threadIdx.y + i][threadIdx.x] = W[(y + i) * HID + x];
    __syncthreads();
    x = blockIdx.y * 32 + threadIdx.x;
    y = blockIdx.x * 32 + threadIdx.y;
    #pragma unroll
    for (int i = 0; i < 32; i += 8)
        g_WhhT[(y + i) * HID + x] = tile[threadIdx.x][threadIdx.y + i];
}

// ---------------- packA: X -> fp16 fragment-ordered tiles (128m x 32k) ----------------
__global__ void __launch_bounds__(256) packA(const float* __restrict__ X) {
    const int kt = blockIdx.x, mb = blockIdx.y;
    uint8_t* dst = g_Apk + ((size_t)mb * KT + kt) * TILEB_A;
    const float* src = X + (size_t)(mb * 128) * VOCAB + kt * 32;
    #pragma unroll
    for (int i = 0; i < 8; i++) {
        int idx = threadIdx.x + i * 256;
        int m = idx >> 4, p = idx & 15;
        float2 v = *(const float2*)&src[(size_t)m * VOCAB + p * 2];
        __half2 h = __floats2half2_rn(v.x, v.y);
        *(uint32_t*)(dst + m * 64 + koff_pair(p)) = *(uint32_t*)&h;
    }
}

// ---------------- packB: W_xh^T -> fp16 fragment-ordered tiles (64n x 32k) ----------------
__global__ void __launch_bounds__(256) packB(const float* __restrict__ Wxh) {
    __shared__ float s[32][68];
    const int kt = blockIdx.x, nb = blockIdx.y;
    uint8_t* dst = g_Bpk + ((size_t)nb * KT + kt) * TILEB_B;
    #pragma unroll
    for (int i = 0; i < 8; i++) {
        int idx = threadIdx.x + i * 256;
        int kk = idx >> 6, n = idx & 63;
        s[kk][n] = Wxh[(size_t)(kt * 32 + kk) * HID + nb * 64 + n];
    }
    __syncthreads();
    #pragma unroll
    for (int i = 0; i < 4; i++) {
        int idx = threadIdx.x + i * 256;
        int n = idx >> 4, p = idx & 15;
        __half2 h = __floats2half2_rn(s[2 * p][n], s[2 * p + 1][n]);
        *(uint32_t*)(dst + n * 64 + koff_pair(p)) = *(uint32_t*)&h;
    }
}

// ---------------- Phase 1: Z = X @ W_xh  (fp16 mma.sync, 2 CTAs/SM) ----------------
// grid (16 nb, 50 mb), 288 threads = 8 compute warps (4m x 2n, warp tile 32x32)
// + 1 producer warp. Tile 128x64, BK=32, NS=3 stages, no __syncthreads in mainloop.
// 36KB dynamic smem, ~95 regs -> 2 CTAs resident per SM fill each other's bubbles.
extern __shared__ uint8_t dsm[];
__global__ void __launch_bounds__(288, 2) gemm_fp16() {
    __shared__ __align__(8) uint64_t s_full[NS], s_empty[NS];

    const int tid  = threadIdx.x;
    const int lane = tid & 31;
    const int warp = tid >> 5;         // 0..8
    const int nb   = blockIdx.x, mb = blockIdx.y;

    uint32_t mb_full[NS], mb_empty[NS];
    #pragma unroll
    for (int s = 0; s < NS; s++) {
        mb_full[s]  = s2u(&s_full[s]);
        mb_empty[s] = s2u(&s_empty[s]);
    }
    if (tid == 0) {
        #pragma unroll
        for (int s = 0; s < NS; s++) {
            mbar_init(mb_full[s], 1);
            mbar_init(mb_empty[s], 256);   // 8 compute warps x 32 lanes
        }
    }
    __syncthreads();

    const uint8_t* Ab = g_Apk + (size_t)mb * KT * TILEB_A;
    const uint8_t* Bb = g_Bpk + (size_t)nb * KT * TILEB_B;
    const uint32_t smem0 = s2u(dsm);

    if (warp == 8) {
        // ---------- producer ----------
        if (lane == 0) {
            #pragma unroll
            for (int f = 0; f < NS; f++) {
                mbar_expect(mb_full[f], STG_STRIDE);
                bulk_g2s(smem0 + f * STG_STRIDE,           Ab + (size_t)f * TILEB_A, TILEB_A, mb_full[f]);
                bulk_g2s(smem0 + f * STG_STRIDE + TILEB_A, Bb + (size_t)f * TILEB_B, TILEB_B, mb_full[f]);
            }
            for (int f = NS; f < KT; f++) {
                const int s  = f % NS;
                const int ph = ((f / NS) - 1) & 1;
                mbar_wait(mb_empty[s], ph);
                mbar_expect(mb_full[s], STG_STRIDE);
                bulk_g2s(smem0 + s * STG_STRIDE,           Ab + (size_t)f * TILEB_A, TILEB_A, mb_full[s]);
                bulk_g2s(smem0 + s * STG_STRIDE + TILEB_A, Bb + (size_t)f * TILEB_B, TILEB_B, mb_full[s]);
            }
        }
        return;
    }

    // ---------- consumers ----------
    const int wm = warp & 3;       // m offset wm*32
    const int wn = warp >> 2;      // n offset wn*32
    const int g  = lane >> 2;
    const int tg = lane & 3;

    float acc[2][4][4];
    #pragma unroll
    for (int mi = 0; mi < 2; mi++)
        #pragma unroll
        for (int ni = 0; ni < 4; ni++)
            #pragma unroll
            for (int j = 0; j < 4; j++) acc[mi][ni][j] = 0.0f;

    const uint32_t a_off = (uint32_t)((wm * 32 + g) * 64 + tg * 16);
    const uint32_t b_off = (uint32_t)((wn * 32 + g) * 64 + tg * 16) + TILEB_A;

    #pragma unroll 1
    for (int kt = 0; kt < KT; kt++) {
        const int s  = kt % NS;
        const int ph = (kt / NS) & 1;
        mbar_wait(mb_full[s], ph);

        const uint8_t* stg = dsm + s * STG_STRIDE;

        uint4 aL0 = *(const uint4*)(stg + a_off);
        uint4 aH0 = *(const uint4*)(stg + a_off + 512);
        uint4 aL1 = *(const uint4*)(stg + a_off + 1024);
        uint4 aH1 = *(const uint4*)(stg + a_off + 1536);
        uint4 bf[4];
        #pragma unroll
        for (int ni = 0; ni < 4; ni++)
            bf[ni] = *(const uint4*)(stg + b_off + ni * 512);

        mbar_arrive(mb_empty[s]);   // release: orders this thread's LDS before signal

        #pragma unroll
        for (int ni = 0; ni < 4; ni++)
            hmma(acc[0][ni], aL0.x, aH0.x, aL0.y, aH0.y, bf[ni].x, bf[ni].y);
        #pragma unroll
        for (int ni = 0; ni < 4; ni++)
            hmma(acc[1][ni], aL1.x, aH1.x, aL1.y, aH1.y, bf[ni].x, bf[ni].y);
        #pragma unroll
        for (int ni = 0; ni < 4; ni++)
            hmma(acc[0][ni], aL0.z, aH0.z, aL0.w, aH0.w, bf[ni].z, bf[ni].w);
        #pragma unroll
        for (int ni = 0; ni < 4; ni++)
            hmma(acc[1][ni], aL1.z, aH1.z, aL1.w, aH1.w, bf[ni].z, bf[ni].w);
    }

    // store C
    const int cg = tg * 2;
    #pragma unroll
    for (int mi = 0; mi < 2; mi++) {
        #pragma unroll
        for (int ni = 0; ni < 4; ni++) {
            int row = mb * 128 + wm * 32 + mi * 16 + g;
            int col = nb * 64 + wn * 32 + ni * 8 + cg;
            g_Z[(size_t)row * HID + col]           = acc[mi][ni][0];
            g_Z[(size_t)row * HID + col + 1]       = acc[mi][ni][1];
            g_Z[(size_t)(row + 8) * HID + col]     = acc[mi][ni][2];
            g_Z[(size_t)(row + 8) * HID + col + 1] = acc[mi][ni][3];
        }
    }
}

// ---------------- distributed grid barrier ----------------
__device__ __forceinline__ void grid_sync2(int t) {
    __syncthreads();
    const int tid = threadIdx.x;
    if (tid == 0) {
        __threadfence();
        *(volatile int*)&g_flags[blockIdx.x * 32] = t + 1;
    }
    if (blockIdx.x == 0) {
        if (tid < NBLK_RECUR)
            while (*(volatile int*)&g_flags[tid * 32] <= t) { }
        __syncthreads();
        if (tid == 0) { __threadfence(); g_rel = t + 1; }
    }
    if (tid == 0) { while (g_rel <= t) { } }
    __syncthreads();
}

// ---------------- Phase 2: persistent recurrence ----------------
__global__ void __launch_bounds__(256) rnn_recur(const float* __restrict__ b_h) {
    __shared__ float w_s[8][1028];
    __shared__ float sh[BSZ][132];

    const int tid = threadIdx.x;
    const int r   = tid >> 3;
    const int c   = tid & 7;
    const int col = blockIdx.x * 8 + c;

    #pragma unroll
    for (int j = tid; j < 2048; j += 256) {
        int cc = j >> 8, kq = (j & 255) * 4;
        *(float4*)&w_s[cc][kq] =
            *(const float4*)&g_WhhT[(size_t)(blockIdx.x * 8 + cc) * HID + kq];
    }
    const float bias = b_h[col];
    const uint32_t sh_r = s2u(&sh[0][0]) + r * 528;
    const uint32_t ws_c = s2u(&w_s[0][0]) + c * 4112;
    __syncthreads();

    for (int t = 0; t < T_STEPS; t++) {
        const float* hin  = g_h[t & 1];
        float*       hout = g_h[(t + 1) & 1];
        const float* Zt   = g_Z + (size_t)t * BSZ * HID;

        unsigned long long a0 = 0ull, a1 = 0ull;
        for (int kc = 0; kc < HID; kc += 128) {
            __syncthreads();
            #pragma unroll
            for (int j = tid; j < 800; j += 256) {
                int rr = j >> 5, kq = (j & 31) * 4;
                *(float4*)&sh[rr][kq] = *(const float4*)&hin[rr * HID + kc + kq];
            }
            __syncthreads();
            if (r < BSZ) {
                #pragma unroll
                for (int i = 0; i < 32; i++) {
                    unsigned long long h01, h23, v01, v23;
                    asm("ld.shared.v2.u64 {%0,%1}, [%2];" : "=l"(h01), "=l"(h23) : "r"(sh_r + i * 16));
                    asm("ld.shared.v2.u64 {%0,%1}, [%2];" : "=l"(v01), "=l"(v23) : "r"(ws_c + (kc + i * 4) * 4));
                    asm("fma.rn.f32x2 %0, %1, %2, %0;" : "+l"(a0) : "l"(h01), "l"(v01));
                    asm("fma.rn.f32x2 %0, %1, %2, %0;" : "+l"(a1) : "l"(h23), "l"(v23));
                }
            }
        }
        if (r < BSZ) {
            float x0, x1, y0, y1;
            asm("mov.b64 {%0,%1}, %2;" : "=f"(x0), "=f"(x1) : "l"(a0));
            asm("mov.b64 {%0,%1}, %2;" : "=f"(y0), "=f"(y1) : "l"(a1));
            float v = (x0 + x1) + (y0 + y1);
            hout[r * HID + col] = tanhf(Zt[r * HID + col] + v + bias);
        }
        grid_sync2(t);
    }
}

// ---------------- Phase 3: pool + FC + softmax ----------------
__global__ void final_k(const float* __restrict__ fc_w,
                        const float* __restrict__ fc_b,
                        float* __restrict__ out) {
    __shared__ float s0[256], s1[256];
    const float* h = g_h[0];
    int tid = threadIdx.x;
    float l0 = 0.0f, l1 = 0.0f;
    for (int j = tid; j < HID; j += 256) {
        float p = 0.0f;
        #pragma unroll
        for (int rr = 0; rr < BSZ; rr++) p += h[rr * HID + j];
        p *= (1.0f / (float)BSZ);
        l0 += p * fc_w[j * NCLS + 0];
        l1 += p * fc_w[j * NCLS + 1];
    }
    s0[tid] = l0; s1[tid] = l1;
    __syncthreads();
    for (int s = 128; s; s >>= 1) {
        if (tid < s) { s0[tid] += s0[tid + s]; s1[tid] += s1[tid + s]; }
        __syncthreads();
    }
    if (tid == 0) {
        float a = s0[0] + fc_b[0];
        float b = s1[0] + fc_b[1];
        float m = fmaxf(a, b);
        float e0 = expf(a - m), e1 = expf(b - m);
        float inv = 1.0f / (e0 + e1);
        out[0] = e0 * inv;
        out[1] = e1 * inv;
    }
}

// ---------------- launch ----------------
extern "C" void kernel_launch(void* const* d_in, const int* in_sizes, int n_in,
                              void* d_out, int out_size) {
    const float* X   = (const float*)d_in[0];
    const float* Wxh = (const float*)d_in[1];
    const float* Whh = (const float*)d_in[2];
    const float* bh  = (const float*)d_in[3];
    const float* fcw = (const float*)d_in[4];
    const float* fcb = (const float*)d_in[5];
    float* out = (float*)d_out;

    init_k<<<100, 256>>>();
    transpose_k<<<dim3(32, 32), dim3(32, 8)>>>(Whh);
    packA<<<dim3(KT, 50), 256>>>(X);
    packB<<<dim3(KT, 16), 256>>>(Wxh);
    gemm_fp16<<<dim3(16, 50), 288, NS * STG_STRIDE>>>();
    rnn_recur<<<NBLK_RECUR, 256>>>(bh);
    final_k<<<1, 256>>>(fcw, fcb, out);
}

// round 12
// speedup vs baseline: 1.5511x; 1.5511x over previous
#include <cuda_runtime.h>
#include <cuda_fp16.h>
#include <cstdint>

#define T_STEPS 256
#define BSZ     25
#define VOCAB   32000
#define HID     1024
#define NCLS    2
#define MROWS   6400
#define NBLK_RECUR 128
#define KT      1000           // k-tiles of 32 (32000/32)
#define TILEB   8192           // bytes per packed tile (128 rows x 32 k x fp16)

// ---------------- device scratch ----------------
__device__ float g_Z[MROWS * HID];                        // 26 MB
__device__ float g_WhhT[HID * HID];                       // 4 MB
__device__ float g_h[2][BSZ * HID];
__device__ __align__(256) uint8_t g_Apk[(size_t)50 * KT * TILEB];  // 409.6 MB
__device__ __align__(256) uint8_t g_Bpk[(size_t)8  * KT * TILEB];  // 65.5 MB
__device__ int   g_flags[NBLK_RECUR * 32];
__device__ volatile int g_rel;

// ---------------- helpers ----------------
__device__ __forceinline__ uint32_t s2u(const void* p) {
    uint32_t a;
    asm("{ .reg .u64 t; cvta.to.shared.u64 t, %1; cvt.u32.u64 %0, t; }" : "=r"(a) : "l"(p));
    return a;
}
__device__ __forceinline__ void mbar_init(uint32_t m, uint32_t c) {
    asm volatile("mbarrier.init.shared.b64 [%0], %1;" :: "r"(m), "r"(c) : "memory");
}
__device__ __forceinline__ void mbar_expect(uint32_t m, uint32_t bytes) {
    asm volatile("mbarrier.arrive.expect_tx.shared.b64 _, [%0], %1;" :: "r"(m), "r"(bytes) : "memory");
}
__device__ __forceinline__ void mbar_wait(uint32_t m, uint32_t ph) {
    asm volatile(
        "{\n\t.reg .pred P;\n\t"
        "W%=:\n\t"
        "mbarrier.try_wait.parity.acquire.cta.shared::cta.b64 P, [%0], %1, 0x989680;\n\t"
        "@P bra.uni D%=;\n\t"
        "bra.uni W%=;\n\t"
        "D%=:\n\t}" :: "r"(m), "r"(ph) : "memory");
}
__device__ __forceinline__ void bulk_g2s(uint32_t dst, const void* src, uint32_t bytes, uint32_t mbar) {
    asm volatile(
        "cp.async.bulk.shared::cluster.global.mbarrier::complete_tx::bytes [%0], [%1], %2, [%3];"
        :: "r"(dst), "l"(src), "r"(bytes), "r"(mbar) : "memory");
}
__device__ __forceinline__ void hmma(float* c, uint32_t a0, uint32_t a1, uint32_t a2,
                                     uint32_t a3, uint32_t b0, uint32_t b1) {
    asm volatile(
        "mma.sync.aligned.m16n8k16.row.col.f32.f16.f16.f32 "
        "{%0,%1,%2,%3}, {%4,%5,%6,%7}, {%8,%9}, {%0,%1,%2,%3};\n"
        : "+f"(c[0]), "+f"(c[1]), "+f"(c[2]), "+f"(c[3])
        : "r"(a0), "r"(a1), "r"(a2), "r"(a3), "r"(b0), "r"(b1));
}

// packed in-row byte offset for k-pair p within a 32-k row (fragment-ordered)
__device__ __forceinline__ uint32_t koff_pair(int p) {
    return (uint32_t)((p & 3) * 16 + (p >> 2) * 4);
}

// ---------------- init ----------------
__global__ void init_k() {
    int tid = blockIdx.x * 256 + threadIdx.x;
    if (tid == 0) g_rel = 0;
    if (tid < NBLK_RECUR * 32) g_flags[tid] = 0;
    if (tid < BSZ * HID) g_h[0][tid] = 0.0f;
}

// dummy launch so the GEMM lands in ncu's -s 5 -c 1 capture window
__global__ void dummy_k() {}

// ---------------- W_hh transpose ----------------
__global__ void transpose_k(const float* __restrict__ W) {
    __shared__ float tile[32][33];
    int x = blockIdx.x * 32 + threadIdx.x;
    int y = blockIdx.y * 32 + threadIdx.y;
    #pragma unroll
    for (int i = 0; i < 32; i += 8)
        tile[threadIdx.y + i][threadIdx.x] = W[(y + i) * HID + x];
    __syncthreads();
    x = blockIdx.y * 32 + threadIdx.x;
    y = blockIdx.x * 32 + threadIdx.y;
    #pragma unroll
    for (int i = 0; i < 32; i += 8)
        g_WhhT[(y + i) * HID + x] = tile[threadIdx.x][threadIdx.y + i];
}

// ---------------- packA: X -> fp16 fragment-ordered tiles (128m x 32k) ----------------
__global__ void __launch_bounds__(256) packA(const float* __restrict__ X) {
    const int kt = blockIdx.x, mb = blockIdx.y;
    uint8_t* dst = g_Apk + ((size_t)mb * KT + kt) * TILEB;
    const float* src = X + (size_t)(mb * 128) * VOCAB + kt * 32;
    #pragma unroll
    for (int i = 0; i < 8; i++) {
        int idx = threadIdx.x + i * 256;
        int m = idx >> 4, p = idx & 15;
        float2 v = *(const float2*)&src[(size_t)m * VOCAB + p * 2];
        __half2 h = __floats2half2_rn(v.x, v.y);
        *(uint32_t*)(dst + m * 64 + koff_pair(p)) = *(uint32_t*)&h;
    }
}

// ---------------- packB: W_xh^T -> fp16 fragment-ordered tiles (128n x 32k) ----------------
__global__ void __launch_bounds__(256) packB(const float* __restrict__ Wxh) {
    __shared__ float s[32][132];
    const int kt = blockIdx.x, nb = blockIdx.y;
    uint8_t* dst = g_Bpk + ((size_t)nb * KT + kt) * TILEB;
    #pragma unroll
    for (int i = 0; i < 16; i++) {
        int idx = threadIdx.x + i * 256;
        int kk = idx >> 7, n = idx & 127;
        s[kk][n] = Wxh[(size_t)(kt * 32 + kk) * HID + nb * 128 + n];
    }
    __syncthreads();
    #pragma unroll
    for (int i = 0; i < 8; i++) {
        int idx = threadIdx.x + i * 256;
        int n = idx >> 4, p = idx & 15;
        __half2 h = __floats2half2_rn(s[2 * p][n], s[2 * p + 1][n]);
        *(uint32_t*)(dst + n * 64 + koff_pair(p)) = *(uint32_t*)&h;
    }
}

// ---------------- Phase 1: Z = X @ W_xh  (fp16 mma.sync, 2 CTAs/SM, early refill) ----------------
// grid (8 nb, 50 mb), 256 threads = 8 warps (4m x 2n), warp tile 32x64.
// BK=32, 2-stage. Per iter: wait full -> read all frags -> syncthreads ->
// tid0 refills stage (before compute!) -> 32 HMMAs. 32KB smem, <=128 regs.
__global__ void __launch_bounds__(256, 2) gemm_fp16() {
    __shared__ __align__(128) uint8_t sA[2][TILEB];
    __shared__ __align__(128) uint8_t sB[2][TILEB];
    __shared__ __align__(8) uint64_t s_full[2];

    const int tid  = threadIdx.x;
    const int lane = tid & 31;
    const int warp = tid >> 5;
    const int wm   = warp & 3;
    const int wn   = warp >> 2;
    const int g    = lane >> 2;
    const int tg   = lane & 3;
    const int nb   = blockIdx.x, mb = blockIdx.y;

    const uint32_t mb_full[2] = { s2u(&s_full[0]), s2u(&s_full[1]) };
    if (tid == 0) { mbar_init(mb_full[0], 1); mbar_init(mb_full[1], 1); }
    __syncthreads();

    const uint8_t* Ab = g_Apk + (size_t)mb * KT * TILEB;
    const uint8_t* Bb = g_Bpk + (size_t)nb * KT * TILEB;
    const uint32_t sa0 = s2u(&sA[0][0]), sb0 = s2u(&sB[0][0]);

    if (tid == 0) {
        #pragma unroll
        for (int s = 0; s < 2; s++) {
            mbar_expect(mb_full[s], 2 * TILEB);
            bulk_g2s(sa0 + s * TILEB, Ab + (size_t)s * TILEB, TILEB, mb_full[s]);
            bulk_g2s(sb0 + s * TILEB, Bb + (size_t)s * TILEB, TILEB, mb_full[s]);
        }
    }

    float acc[2][8][4];
    #pragma unroll
    for (int mi = 0; mi < 2; mi++)
        #pragma unroll
        for (int ni = 0; ni < 8; ni++)
            #pragma unroll
            for (int j = 0; j < 4; j++) acc[mi][ni][j] = 0.0f;

    const uint32_t a_off = (uint32_t)((wm * 32 + g) * 64 + tg * 16);
    const uint32_t b_off = (uint32_t)((wn * 64 + g) * 64 + tg * 16);

    #pragma unroll 1
    for (int kt = 0; kt < KT; kt++) {
        const int s  = kt & 1;
        const int ph = (kt >> 1) & 1;
        mbar_wait(mb_full[s], ph);

        const uint8_t* As = sA[s];
        const uint8_t* Bs = sB[s];

        // read ALL fragments for this stage first
        uint4 aL0 = *(const uint4*)(As + a_off);
        uint4 aH0 = *(const uint4*)(As + a_off + 512);
        uint4 aL1 = *(const uint4*)(As + a_off + 1024);
        uint4 aH1 = *(const uint4*)(As + a_off + 1536);
        uint4 bf[8];
        #pragma unroll
        for (int ni = 0; ni < 8; ni++)
            bf[ni] = *(const uint4*)(Bs + b_off + ni * 512);

        // stage is free once every thread has its regs -> refill BEFORE compute
        __syncthreads();
        const int nk = kt + 2;
        if (tid == 0 && nk < KT) {
            mbar_expect(mb_full[s], 2 * TILEB);
            bulk_g2s(sa0 + s * TILEB, Ab + (size_t)nk * TILEB, TILEB, mb_full[s]);
            bulk_g2s(sb0 + s * TILEB, Bb + (size_t)nk * TILEB, TILEB, mb_full[s]);
        }

        // 4 batches of 8 independent HMMAs
        #pragma unroll
        for (int ni = 0; ni < 8; ni++)
            hmma(acc[0][ni], aL0.x, aH0.x, aL0.y, aH0.y, bf[ni].x, bf[ni].y);
        #pragma unroll
        for (int ni = 0; ni < 8; ni++)
            hmma(acc[1][ni], aL1.x, aH1.x, aL1.y, aH1.y, bf[ni].x, bf[ni].y);
        #pragma unroll
        for (int ni = 0; ni < 8; ni++)
            hmma(acc[0][ni], aL0.z, aH0.z, aL0.w, aH0.w, bf[ni].z, bf[ni].w);
        #pragma unroll
        for (int ni = 0; ni < 8; ni++)
            hmma(acc[1][ni], aL1.z, aH1.z, aL1.w, aH1.w, bf[ni].z, bf[ni].w);
    }

    // store C
    const int cg = tg * 2;
    #pragma unroll
    for (int mi = 0; mi < 2; mi++) {
        #pragma unroll
        for (int ni = 0; ni < 8; ni++) {
            int row = mb * 128 + wm * 32 + mi * 16 + g;
            int col = nb * 128 + wn * 64 + ni * 8 + cg;
            g_Z[(size_t)row * HID + col]           = acc[mi][ni][0];
            g_Z[(size_t)row * HID + col + 1]       = acc[mi][ni][1];
            g_Z[(size_t)(row + 8) * HID + col]     = acc[mi][ni][2];
            g_Z[(size_t)(row + 8) * HID + col + 1] = acc[mi][ni][3];
        }
    }
}

// ---------------- distributed grid barrier ----------------
__device__ __forceinline__ void grid_sync2(int t) {
    __syncthreads();
    const int tid = threadIdx.x;
    if (tid == 0) {
        __threadfence();
        *(volatile int*)&g_flags[blockIdx.x * 32] = t + 1;
    }
    if (blockIdx.x == 0) {
        if (tid < NBLK_RECUR)
            while (*(volatile int*)&g_flags[tid * 32] <= t) { }
        __syncthreads();
        if (tid == 0) { __threadfence(); g_rel = t + 1; }
    }
    if (tid == 0) { while (g_rel <= t) { } }
    __syncthreads();
}

// ---------------- Phase 2: persistent recurrence ----------------
__global__ void __launch_bounds__(256) rnn_recur(const float* __restrict__ b_h) {
    __shared__ float w_s[8][1028];
    __shared__ float sh[BSZ][132];

    const int tid = threadIdx.x;
    const int r   = tid >> 3;
    const int c   = tid & 7;
    const int col = blockIdx.x * 8 + c;

    #pragma unroll
    for (int j = tid; j < 2048; j += 256) {
        int cc = j >> 8, kq = (j & 255) * 4;
        *(float4*)&w_s[cc][kq] =
            *(const float4*)&g_WhhT[(size_t)(blockIdx.x * 8 + cc) * HID + kq];
    }
    const float bias = b_h[col];
    const uint32_t sh_r = s2u(&sh[0][0]) + r * 528;
    const uint32_t ws_c = s2u(&w_s[0][0]) + c * 4112;
    __syncthreads();

    for (int t = 0; t < T_STEPS; t++) {
        const float* hin  = g_h[t & 1];
        float*       hout = g_h[(t + 1) & 1];
        const float* Zt   = g_Z + (size_t)t * BSZ * HID;

        unsigned long long a0 = 0ull, a1 = 0ull;
        for (int kc = 0; kc < HID; kc += 128) {
            __syncthreads();
            #pragma unroll
            for (int j = tid; j < 800; j += 256) {
                int rr = j >> 5, kq = (j & 31) * 4;
                *(float4*)&sh[rr][kq] = *(const float4*)&hin[rr * HID + kc + kq];
            }
            __syncthreads();
            if (r < BSZ) {
                #pragma unroll
                for (int i = 0; i < 32; i++) {
                    unsigned long long h01, h23, v01, v23;
                    asm("ld.shared.v2.u64 {%0,%1}, [%2];" : "=l"(h01), "=l"(h23) : "r"(sh_r + i * 16));
                    asm("ld.shared.v2.u64 {%0,%1}, [%2];" : "=l"(v01), "=l"(v23) : "r"(ws_c + (kc + i * 4) * 4));
                    asm("fma.rn.f32x2 %0, %1, %2, %0;" : "+l"(a0) : "l"(h01), "l"(v01));
                    asm("fma.rn.f32x2 %0, %1, %2, %0;" : "+l"(a1) : "l"(h23), "l"(v23));
                }
            }
        }
        if (r < BSZ) {
            float x0, x1, y0, y1;
            asm("mov.b64 {%0,%1}, %2;" : "=f"(x0), "=f"(x1) : "l"(a0));
            asm("mov.b64 {%0,%1}, %2;" : "=f"(y0), "=f"(y1) : "l"(a1));
            float v = (x0 + x1) + (y0 + y1);
            hout[r * HID + col] = tanhf(Zt[r * HID + col] + v + bias);
        }
        grid_sync2(t);
    }
}

// ---------------- Phase 3: pool + FC + softmax ----------------
__global__ void final_k(const float* __restrict__ fc_w,
                        const float* __restrict__ fc_b,
                        float* __restrict__ out) {
    __shared__ float s0[256], s1[256];
    const float* h = g_h[0];
    int tid = threadIdx.x;
    float l0 = 0.0f, l1 = 0.0f;
    for (int j = tid; j < HID; j += 256) {
        float p = 0.0f;
        #pragma unroll
        for (int rr = 0; rr < BSZ; rr++) p += h[rr * HID + j];
        p *= (1.0f / (float)BSZ);
        l0 += p * fc_w[j * NCLS + 0];
        l1 += p * fc_w[j * NCLS + 1];
    }
    s0[tid] = l0; s1[tid] = l1;
    __syncthreads();
    for (int s = 128; s; s >>= 1) {
        if (tid < s) { s0[tid] += s0[tid + s]; s1[tid] += s1[tid + s]; }
        __syncthreads();
    }
    if (tid == 0) {
        float a = s0[0] + fc_b[0];
        float b = s1[0] + fc_b[1];
        float m = fmaxf(a, b);
        float e0 = expf(a - m), e1 = expf(b - m);
        float inv = 1.0f / (e0 + e1);
        out[0] = e0 * inv;
        out[1] = e1 * inv;
    }
}

// ---------------- launch ----------------
extern "C" void kernel_launch(void* const* d_in, const int* in_sizes, int n_in,
                              void* d_out, int out_size) {
    const float* X   = (const float*)d_in[0];
    const float* Wxh = (const float*)d_in[1];
    const float* Whh = (const float*)d_in[2];
    const float* bh  = (const float*)d_in[3];
    const float* fcw = (const float*)d_in[4];
    const float* fcb = (const float*)d_in[5];
    float* out = (float*)d_out;

    init_k<<<100, 256>>>();
    transpose_k<<<dim3(32, 32), dim3(32, 8)>>>(Whh);
    packA<<<dim3(KT, 50), 256>>>(X);
    packB<<<dim3(KT, 8), 256>>>(Wxh);
    dummy_k<<<1, 32>>>();                      // shifts gemm into ncu capture slot
    gemm_fp16<<<dim3(8, 50), 256>>>();
    rnn_recur<<<NBLK_RECUR, 256>>>(bh);
    final_k<<<1, 256>>>(fcw, fcb, out);
}

// round 13
// speedup vs baseline: 1.5528x; 1.0011x over previous
#include <cuda_runtime.h>
#include <cuda_fp16.h>
#include <cstdint>

#define T_STEPS 256
#define BSZ     25
#define VOCAB   32000
#define HID     1024
#define NCLS    2
#define MROWS   6400
#define NBLK_RECUR 128
#define KT      1000           // k-tiles of 32 (32000/32)
#define KSPLIT  2
#define KT_HALF 500
#define TILEB   8192           // bytes per packed tile (128 rows x 32 k x fp16)

// ---------------- device scratch ----------------
__device__ float g_Z[MROWS * HID];                        // 26 MB (k-split 0)
__device__ float g_Z2[MROWS * HID];                       // 26 MB (k-split 1)
__device__ float g_WhhT[HID * HID];                       // 4 MB
__device__ float g_h[2][BSZ * HID];
__device__ __align__(256) uint8_t g_Apk[(size_t)50 * KT * TILEB];  // 409.6 MB
__device__ __align__(256) uint8_t g_Bpk[(size_t)8  * KT * TILEB];  // 65.5 MB
__device__ int   g_flags[NBLK_RECUR * 32];
__device__ volatile int g_rel;

// ---------------- helpers ----------------
__device__ __forceinline__ uint32_t s2u(const void* p) {
    uint32_t a;
    asm("{ .reg .u64 t; cvta.to.shared.u64 t, %1; cvt.u32.u64 %0, t; }" : "=r"(a) : "l"(p));
    return a;
}
__device__ __forceinline__ void mbar_init(uint32_t m, uint32_t c) {
    asm volatile("mbarrier.init.shared.b64 [%0], %1;" :: "r"(m), "r"(c) : "memory");
}
__device__ __forceinline__ void mbar_expect(uint32_t m, uint32_t bytes) {
    asm volatile("mbarrier.arrive.expect_tx.shared.b64 _, [%0], %1;" :: "r"(m), "r"(bytes) : "memory");
}
__device__ __forceinline__ void mbar_wait(uint32_t m, uint32_t ph) {
    asm volatile(
        "{\n\t.reg .pred P;\n\t"
        "W%=:\n\t"
        "mbarrier.try_wait.parity.acquire.cta.shared::cta.b64 P, [%0], %1, 0x989680;\n\t"
        "@P bra.uni D%=;\n\t"
        "bra.uni W%=;\n\t"
        "D%=:\n\t}" :: "r"(m), "r"(ph) : "memory");
}
__device__ __forceinline__ void bulk_g2s(uint32_t dst, const void* src, uint32_t bytes, uint32_t mbar) {
    asm volatile(
        "cp.async.bulk.shared::cluster.global.mbarrier::complete_tx::bytes [%0], [%1], %2, [%3];"
        :: "r"(dst), "l"(src), "r"(bytes), "r"(mbar) : "memory");
}
__device__ __forceinline__ void hmma(float* c, uint32_t a0, uint32_t a1, uint32_t a2,
                                     uint32_t a3, uint32_t b0, uint32_t b1) {
    asm volatile(
        "mma.sync.aligned.m16n8k16.row.col.f32.f16.f16.f32 "
        "{%0,%1,%2,%3}, {%4,%5,%6,%7}, {%8,%9}, {%0,%1,%2,%3};\n"
        : "+f"(c[0]), "+f"(c[1]), "+f"(c[2]), "+f"(c[3])
        : "r"(a0), "r"(a1), "r"(a2), "r"(a3), "r"(b0), "r"(b1));
}

// packed in-row byte offset for k-pair p within a 32-k row (fragment-ordered)
__device__ __forceinline__ uint32_t koff_pair(int p) {
    return (uint32_t)((p & 3) * 16 + (p >> 2) * 4);
}

// ---------------- init ----------------
__global__ void init_k() {
    int tid = blockIdx.x * 256 + threadIdx.x;
    if (tid == 0) g_rel = 0;
    if (tid < NBLK_RECUR * 32) g_flags[tid] = 0;
    if (tid < BSZ * HID) g_h[0][tid] = 0.0f;
}

// ---------------- W_hh transpose ----------------
__global__ void transpose_k(const float* __restrict__ W) {
    __shared__ float tile[32][33];
    int x = blockIdx.x * 32 + threadIdx.x;
    int y = blockIdx.y * 32 + threadIdx.y;
    #pragma unroll
    for (int i = 0; i < 32; i += 8)
        tile[threadIdx.y + i][threadIdx.x] = W[(y + i) * HID + x];
    __syncthreads();
    x = blockIdx.y * 32 + threadIdx.x;
    y = blockIdx.x * 32 + threadIdx.y;
    #pragma unroll
    for (int i = 0; i < 32; i += 8)
        g_WhhT[(y + i) * HID + x] = tile[threadIdx.x][threadIdx.y + i];
}

// ---------------- pack_all: A (y<50) and B (y>=50) fp16 fragment-ordered tiles ----------------
__global__ void __launch_bounds__(256) pack_all(const float* __restrict__ X,
                                                const float* __restrict__ Wxh) {
    const int kt = blockIdx.x;
    const int y  = blockIdx.y;
    if (y < 50) {
        // ---- packA: tile (kt, mb=y): 128 m-rows x 32 k ----
        uint8_t* dst = g_Apk + ((size_t)y * KT + kt) * TILEB;
        const float* src = X + (size_t)(y * 128) * VOCAB + kt * 32;
        #pragma unroll
        for (int i = 0; i < 8; i++) {
            int idx = threadIdx.x + i * 256;
            int m = idx >> 4, p = idx & 15;
            float2 v = *(const float2*)&src[(size_t)m * VOCAB + p * 2];
            __half2 h = __floats2half2_rn(v.x, v.y);
            *(uint32_t*)(dst + m * 64 + koff_pair(p)) = *(uint32_t*)&h;
        }
    } else {
        // ---- packB: tile (kt, nb=y-50): 128 n-rows x 32 k (transpose via smem) ----
        __shared__ float s[32][132];
        const int nb = y - 50;
        uint8_t* dst = g_Bpk + ((size_t)nb * KT + kt) * TILEB;
        #pragma unroll
        for (int i = 0; i < 16; i++) {
            int idx = threadIdx.x + i * 256;
            int kk = idx >> 7, n = idx & 127;
            s[kk][n] = Wxh[(size_t)(kt * 32 + kk) * HID + nb * 128 + n];
        }
        __syncthreads();
        #pragma unroll
        for (int i = 0; i < 8; i++) {
            int idx = threadIdx.x + i * 256;
            int n = idx >> 4, p = idx & 15;
            __half2 h = __floats2half2_rn(s[2 * p][n], s[2 * p + 1][n]);
            *(uint32_t*)(dst + n * 64 + koff_pair(p)) = *(uint32_t*)&h;
        }
    }
}

// ---------------- Phase 1: Z = X @ W_xh  (fp16 mma.sync, split-K=2) ----------------
// grid (8 nb, 50 mb, 2 kz), 256 threads = 8 warps (4m x 2n), warp tile 32x64.
// BK=32, 2-stage bulk pipeline, early refill. kz picks k-range and Z buffer.
// 800 CTAs at occ 2 (n_conc 296) -> 3 waves, 90% utilization (vs 67.6% at 400).
__global__ void __launch_bounds__(256, 2) gemm_fp16() {
    __shared__ __align__(128) uint8_t sA[2][TILEB];
    __shared__ __align__(128) uint8_t sB[2][TILEB];
    __shared__ __align__(8) uint64_t s_full[2];

    const int tid  = threadIdx.x;
    const int lane = tid & 31;
    const int warp = tid >> 5;
    const int wm   = warp & 3;
    const int wn   = warp >> 2;
    const int g    = lane >> 2;
    const int tg   = lane & 3;
    const int nb   = blockIdx.x, mb = blockIdx.y, kz = blockIdx.z;
    const int kt0  = kz * KT_HALF;

    const uint32_t mb_full[2] = { s2u(&s_full[0]), s2u(&s_full[1]) };
    if (tid == 0) { mbar_init(mb_full[0], 1); mbar_init(mb_full[1], 1); }
    __syncthreads();

    const uint8_t* Ab = g_Apk + (size_t)mb * KT * TILEB;
    const uint8_t* Bb = g_Bpk + (size_t)nb * KT * TILEB;
    const uint32_t sa0 = s2u(&sA[0][0]), sb0 = s2u(&sB[0][0]);

    if (tid == 0) {
        #pragma unroll
        for (int s = 0; s < 2; s++) {
            mbar_expect(mb_full[s], 2 * TILEB);
            bulk_g2s(sa0 + s * TILEB, Ab + (size_t)(kt0 + s) * TILEB, TILEB, mb_full[s]);
            bulk_g2s(sb0 + s * TILEB, Bb + (size_t)(kt0 + s) * TILEB, TILEB, mb_full[s]);
        }
    }

    float acc[2][8][4];
    #pragma unroll
    for (int mi = 0; mi < 2; mi++)
        #pragma unroll
        for (int ni = 0; ni < 8; ni++)
            #pragma unroll
            for (int j = 0; j < 4; j++) acc[mi][ni][j] = 0.0f;

    const uint32_t a_off = (uint32_t)((wm * 32 + g) * 64 + tg * 16);
    const uint32_t b_off = (uint32_t)((wn * 64 + g) * 64 + tg * 16);

    #pragma unroll 1
    for (int it = 0; it < KT_HALF; it++) {
        const int s  = it & 1;
        const int ph = (it >> 1) & 1;
        mbar_wait(mb_full[s], ph);

        const uint8_t* As = sA[s];
        const uint8_t* Bs = sB[s];

        uint4 aL0 = *(const uint4*)(As + a_off);
        uint4 aH0 = *(const uint4*)(As + a_off + 512);
        uint4 aL1 = *(const uint4*)(As + a_off + 1024);
        uint4 aH1 = *(const uint4*)(As + a_off + 1536);
        uint4 bf[8];
        #pragma unroll
        for (int ni = 0; ni < 8; ni++)
            bf[ni] = *(const uint4*)(Bs + b_off + ni * 512);

        // stage free once all threads hold their regs -> refill BEFORE compute
        __syncthreads();
        const int nk = it + 2;
        if (tid == 0 && nk < KT_HALF) {
            mbar_expect(mb_full[s], 2 * TILEB);
            bulk_g2s(sa0 + s * TILEB, Ab + (size_t)(kt0 + nk) * TILEB, TILEB, mb_full[s]);
            bulk_g2s(sb0 + s * TILEB, Bb + (size_t)(kt0 + nk) * TILEB, TILEB, mb_full[s]);
        }

        #pragma unroll
        for (int ni = 0; ni < 8; ni++)
            hmma(acc[0][ni], aL0.x, aH0.x, aL0.y, aH0.y, bf[ni].x, bf[ni].y);
        #pragma unroll
        for (int ni = 0; ni < 8; ni++)
            hmma(acc[1][ni], aL1.x, aH1.x, aL1.y, aH1.y, bf[ni].x, bf[ni].y);
        #pragma unroll
        for (int ni = 0; ni < 8; ni++)
            hmma(acc[0][ni], aL0.z, aH0.z, aL0.w, aH0.w, bf[ni].z, bf[ni].w);
        #pragma unroll
        for (int ni = 0; ni < 8; ni++)
            hmma(acc[1][ni], aL1.z, aH1.z, aL1.w, aH1.w, bf[ni].z, bf[ni].w);
    }

    // store C to the split's buffer
    float* Zo = (kz == 0) ? g_Z : g_Z2;
    const int cg = tg * 2;
    #pragma unroll
    for (int mi = 0; mi < 2; mi++) {
        #pragma unroll
        for (int ni = 0; ni < 8; ni++) {
            int row = mb * 128 + wm * 32 + mi * 16 + g;
            int col = nb * 128 + wn * 64 + ni * 8 + cg;
            Zo[(size_t)row * HID + col]           = acc[mi][ni][0];
            Zo[(size_t)row * HID + col + 1]       = acc[mi][ni][1];
            Zo[(size_t)(row + 8) * HID + col]     = acc[mi][ni][2];
            Zo[(size_t)(row + 8) * HID + col + 1] = acc[mi][ni][3];
        }
    }
}

// ---------------- distributed grid barrier ----------------
__device__ __forceinline__ void grid_sync2(int t) {
    __syncthreads();
    const int tid = threadIdx.x;
    if (tid == 0) {
        __threadfence();
        *(volatile int*)&g_flags[blockIdx.x * 32] = t + 1;
    }
    if (blockIdx.x == 0) {
        if (tid < NBLK_RECUR)
            while (*(volatile int*)&g_flags[tid * 32] <= t) { }
        __syncthreads();
        if (tid == 0) { __threadfence(); g_rel = t + 1; }
    }
    if (tid == 0) { while (g_rel <= t) { } }
    __syncthreads();
}

// ---------------- Phase 2: persistent recurrence ----------------
__global__ void __launch_bounds__(256) rnn_recur(const float* __restrict__ b_h) {
    __shared__ float w_s[8][1028];
    __shared__ float sh[BSZ][132];

    const int tid = threadIdx.x;
    const int r   = tid >> 3;
    const int c   = tid & 7;
    const int col = blockIdx.x * 8 + c;

    #pragma unroll
    for (int j = tid; j < 2048; j += 256) {
        int cc = j >> 8, kq = (j & 255) * 4;
        *(float4*)&w_s[cc][kq] =
            *(const float4*)&g_WhhT[(size_t)(blockIdx.x * 8 + cc) * HID + kq];
    }
    const float bias = b_h[col];
    const uint32_t sh_r = s2u(&sh[0][0]) + r * 528;
    const uint32_t ws_c = s2u(&w_s[0][0]) + c * 4112;
    __syncthreads();

    for (int t = 0; t < T_STEPS; t++) {
        const float* hin  = g_h[t & 1];
        float*       hout = g_h[(t + 1) & 1];
        const float* Z1t  = g_Z  + (size_t)t * BSZ * HID;
        const float* Z2t  = g_Z2 + (size_t)t * BSZ * HID;

        unsigned long long a0 = 0ull, a1 = 0ull;
        for (int kc = 0; kc < HID; kc += 128) {
            __syncthreads();
            #pragma unroll
            for (int j = tid; j < 800; j += 256) {
                int rr = j >> 5, kq = (j & 31) * 4;
                *(float4*)&sh[rr][kq] = *(const float4*)&hin[rr * HID + kc + kq];
            }
            __syncthreads();
            if (r < BSZ) {
                #pragma unroll
                for (int i = 0; i < 32; i++) {
                    unsigned long long h01, h23, v01, v23;
                    asm("ld.shared.v2.u64 {%0,%1}, [%2];" : "=l"(h01), "=l"(h23) : "r"(sh_r + i * 16));
                    asm("ld.shared.v2.u64 {%0,%1}, [%2];" : "=l"(v01), "=l"(v23) : "r"(ws_c + (kc + i * 4) * 4));
                    asm("fma.rn.f32x2 %0, %1, %2, %0;" : "+l"(a0) : "l"(h01), "l"(v01));
                    asm("fma.rn.f32x2 %0, %1, %2, %0;" : "+l"(a1) : "l"(h23), "l"(v23));
                }
            }
        }
        if (r < BSZ) {
            float x0, x1, y0, y1;
            asm("mov.b64 {%0,%1}, %2;" : "=f"(x0), "=f"(x1) : "l"(a0));
            asm("mov.b64 {%0,%1}, %2;" : "=f"(y0), "=f"(y1) : "l"(a1));
            float v = (x0 + x1) + (y0 + y1);
            int idx = r * HID + col;
            hout[idx] = tanhf(Z1t[idx] + Z2t[idx] + v + bias);
        }
        grid_sync2(t);
    }
}

// ---------------- Phase 3: pool + FC + softmax ----------------
__global__ void final_k(const float* __restrict__ fc_w,
                        const float* __restrict__ fc_b,
                        float* __restrict__ out) {
    __shared__ float s0[256], s1[256];
    const float* h = g_h[0];
    int tid = threadIdx.x;
    float l0 = 0.0f, l1 = 0.0f;
    for (int j = tid; j < HID; j += 256) {
        float p = 0.0f;
        #pragma unroll
        for (int rr = 0; rr < BSZ; rr++) p += h[rr * HID + j];
        p *= (1.0f / (float)BSZ);
        l0 += p * fc_w[j * NCLS + 0];
        l1 += p * fc_w[j * NCLS + 1];
    }
    s0[tid] = l0; s1[tid] = l1;
    __syncthreads();
    for (int s = 128; s; s >>= 1) {
        if (tid < s) { s0[tid] += s0[tid + s]; s1[tid] += s1[tid + s]; }
        __syncthreads();
    }
    if (tid == 0) {
        float a = s0[0] + fc_b[0];
        float b = s1[0] + fc_b[1];
        float m = fmaxf(a, b);
        float e0 = expf(a - m), e1 = expf(b - m);
        float inv = 1.0f / (e0 + e1);
        out[0] = e0 * inv;
        out[1] = e1 * inv;
    }
}

// ---------------- launch ----------------
extern "C" void kernel_launch(void* const* d_in, const int* in_sizes, int n_in,
                              void* d_out, int out_size) {
    const float* X   = (const float*)d_in[0];
    const float* Wxh = (const float*)d_in[1];
    const float* Whh = (const float*)d_in[2];
    const float* bh  = (const float*)d_in[3];
    const float* fcw = (const float*)d_in[4];
    const float* fcb = (const float*)d_in[5];
    float* out = (float*)d_out;

    init_k<<<100, 256>>>();                          // launch 1
    transpose_k<<<dim3(32, 32), dim3(32, 8)>>>(Whh); // launch 2
    pack_all<<<dim3(KT, 58), 256>>>(X, Wxh);         // launch 3
    gemm_fp16<<<dim3(8, 50, KSPLIT), 256>>>();       // launch 4  <- ncu capture slot
    rnn_recur<<<NBLK_RECUR, 256>>>(bh);              // launch 5
    final_k<<<1, 256>>>(fcw, fcb, out);              // launch 6
}